// round 2
// baseline (speedup 1.0000x reference)
#include <cuda_runtime.h>
#include <cstdint>

#define SEQ   48
#define BATCH 4096
#define BB    8192
#define DEMB  300
#define DX    304
#define HID   512
#define G4    2048
#define KTOT  816
#define NIT_STEP 51
#define SIN   1025
#define SPAD  1040
#define NROWS 1152
#define NIT_MLP 65
#define BKP   20
#define TILEF (128 * BKP)

// ---------------- scratch ----------------
__device__ float d_Xall[(size_t)SEQ * BB * DX];
__device__ float d_H[2ull * BB * HID];
__device__ float d_C[(size_t)BB * HID];
__device__ float d_Hfp[(size_t)BB * HID];
__device__ float d_Wc[(size_t)G4 * KTOT];
__device__ float d_bc[G4];
__device__ float d_X0[(size_t)BATCH * SPAD];
__device__ float d_Y1[(size_t)BATCH * SPAD];
__device__ float d_Y2[(size_t)BATCH * SPAD];
__device__ float d_NAh[(size_t)BATCH * SPAD];
__device__ float d_NAl[(size_t)BATCH * SPAD];
__device__ float d_W0h[(size_t)NROWS * SPAD];
__device__ float d_W0l[(size_t)NROWS * SPAD];
__device__ float d_W1h[(size_t)NROWS * SPAD];
__device__ float d_W1l[(size_t)NROWS * SPAD];
__device__ float d_b0p[NROWS];
__device__ float d_b1p[NROWS];
__device__ float d_scale[SPAD];
__device__ float d_shift[SPAD];

// ---------------- helpers ----------------
__device__ __forceinline__ float tf32r(float x) {
    uint32_t u;
    asm("cvt.rna.tf32.f32 %0, %1;" : "=r"(u) : "f"(x));
    return __uint_as_float(u);
}
__device__ __forceinline__ void cpa16(void* s, const void* g) {
    uint32_t sa = (uint32_t)__cvta_generic_to_shared(s);
    asm volatile("cp.async.ca.shared.global [%0], [%1], 16;\n" :: "r"(sa), "l"(g));
}
__device__ __forceinline__ void cpa_commit() { asm volatile("cp.async.commit_group;\n"); }
__device__ __forceinline__ void cpa_wait1()  { asm volatile("cp.async.wait_group 1;\n"); }
__device__ __forceinline__ void cpa_wait0()  { asm volatile("cp.async.wait_group 0;\n"); }

__device__ __forceinline__ void mma_tf32(float* c, const uint32_t* a, const uint32_t* b) {
    asm volatile(
        "mma.sync.aligned.m16n8k8.row.col.f32.tf32.tf32.f32 "
        "{%0,%1,%2,%3}, {%4,%5,%6,%7}, {%8,%9}, {%0,%1,%2,%3};\n"
        : "+f"(c[0]), "+f"(c[1]), "+f"(c[2]), "+f"(c[3])
        : "r"(a[0]), "r"(a[1]), "r"(a[2]), "r"(a[3]), "r"(b[0]), "r"(b[1]));
}

// ---------------- prep ----------------
__global__ void k_prep(const float* __restrict__ Wih, const float* __restrict__ Whh,
                       const float* __restrict__ bih, const float* __restrict__ bhh) {
    for (size_t i = (size_t)blockIdx.x * blockDim.x + threadIdx.x;
         i < (size_t)G4 * KTOT; i += (size_t)gridDim.x * blockDim.x) {
        int g = (int)(i / KTOT), k = (int)(i % KTOT);
        float v;
        if (k < HID)              v = Whh[(size_t)g * HID + k];
        else if (k - HID < DEMB)  v = Wih[(size_t)g * DEMB + (k - HID)];
        else                      v = 0.f;
        d_Wc[i] = tf32r(v);
        if (i < G4) d_bc[i] = bih[i] + bhh[i];
    }
}

__global__ void k_padw(const float* __restrict__ src, int which) {
    float* dh = which ? d_W1h : d_W0h;
    float* dl = which ? d_W1l : d_W0l;
    for (size_t i = (size_t)blockIdx.x * blockDim.x + threadIdx.x;
         i < (size_t)NROWS * SPAD; i += (size_t)gridDim.x * blockDim.x) {
        int r = (int)(i / SPAD), c = (int)(i % SPAD);
        float v = (r < SIN && c < SIN) ? src[(size_t)r * SIN + c] : 0.f;
        float h = tf32r(v);
        dh[i] = h;
        dl[i] = tf32r(v - h);
    }
}

__global__ void k_padb(const float* __restrict__ src, int which) {
    float* dst = which ? d_b1p : d_b0p;
    int i = blockIdx.x * blockDim.x + threadIdx.x;
    if (i < NROWS) dst[i] = (i < SIN) ? src[i] : 0.f;
}

__global__ void k_zero() {
    for (size_t i = (size_t)blockIdx.x * blockDim.x + threadIdx.x;
         i < (size_t)BB * HID; i += (size_t)gridDim.x * blockDim.x) {
        d_C[i] = 0.f;
        d_H[i] = 0.f;   // par=0 buffer
    }
}

__global__ void k_gather(const int* __restrict__ prem, const int* __restrict__ hyp,
                         const float* __restrict__ embed) {
    int sb = blockIdx.x;
    int s = sb / BB, b = sb % BB;
    int tok = (b < BATCH) ? prem[s * BATCH + b] : hyp[s * BATCH + (b - BATCH)];
    const float* e = embed + (size_t)tok * DEMB;
    float* dst = d_Xall + (size_t)sb * DX;
    for (int d = threadIdx.x; d < DX; d += blockDim.x)
        dst[d] = (d < DEMB) ? tf32r(e[d]) : 0.f;
}

// ---------------- fused LSTM step ----------------
__global__ void __launch_bounds__(256) k_step(int s, int par) {
    extern __shared__ float sm[];
    float* As = sm;                    // [2][TILEF]
    float* Bs = sm + 2 * TILEF;        // [2][TILEF]
    float* Gs = sm;                    // reused after mainloop, pitch 132

    const int m0 = blockIdx.x * 128;
    const int n0 = blockIdx.y * 32;
    const int tid = threadIdx.x;
    const int lane = tid & 31, warp = tid >> 5;
    const int gid = lane >> 2, tg = lane & 3;
    const int wm = (warp >> 1) * 32;
    const int wn = (warp & 1) * 64;
    const float* Hrd = d_H + (size_t)par * BB * HID;

    float c[2][8][4];
#pragma unroll
    for (int a = 0; a < 2; a++)
#pragma unroll
        for (int b = 0; b < 8; b++)
#pragma unroll
            for (int q = 0; q < 4; q++) c[a][b][q] = 0.f;

    auto loadtile = [&](int it, int buf) {
        int k0 = it * 16;
        float* Ab = As + buf * TILEF;
        float* Bb = Bs + buf * TILEF;
#pragma unroll
        for (int u = 0; u < 2; u++) {
            int f = tid + u * 256;
            int r = f >> 2, c4 = f & 3;
            const float* ga = (k0 < HID)
                ? (Hrd + (size_t)(m0 + r) * HID + k0 + c4 * 4)
                : (d_Xall + ((size_t)s * BB + m0 + r) * DX + (k0 - HID) + c4 * 4);
            cpa16(Ab + r * BKP + c4 * 4, ga);
            const float* gb = d_Wc + (size_t)((r >> 5) * HID + n0 + (r & 31)) * KTOT + k0 + c4 * 4;
            cpa16(Bb + r * BKP + c4 * 4, gb);
        }
        cpa_commit();
    };

    auto compute = [&](int buf) {
        const float* Ab = As + buf * TILEF;
        const float* Bb = Bs + buf * TILEF;
#pragma unroll
        for (int kk = 0; kk < 16; kk += 8) {
            uint32_t af[2][4], bf[8][2];
#pragma unroll
            for (int mf = 0; mf < 2; mf++) {
                int r = wm + mf * 16 + gid;
                af[mf][0] = __float_as_uint(Ab[r * BKP + kk + tg]);
                af[mf][1] = __float_as_uint(Ab[(r + 8) * BKP + kk + tg]);
                af[mf][2] = __float_as_uint(Ab[r * BKP + kk + tg + 4]);
                af[mf][3] = __float_as_uint(Ab[(r + 8) * BKP + kk + tg + 4]);
            }
#pragma unroll
            for (int nf = 0; nf < 8; nf++) {
                int n = wn + nf * 8 + gid;
                bf[nf][0] = __float_as_uint(Bb[n * BKP + kk + tg]);
                bf[nf][1] = __float_as_uint(Bb[n * BKP + kk + tg + 4]);
            }
#pragma unroll
            for (int mf = 0; mf < 2; mf++)
#pragma unroll
                for (int nf = 0; nf < 8; nf++)
                    mma_tf32(c[mf][nf], af[mf], bf[nf]);
        }
    };

    loadtile(0, 0);
#pragma unroll 1
    for (int it = 0; it < NIT_STEP; ++it) {
        if (it + 1 < NIT_STEP) { loadtile(it + 1, (it + 1) & 1); cpa_wait1(); }
        else                   { cpa_wait0(); }
        __syncthreads();
        compute(it & 1);
        __syncthreads();
    }

#pragma unroll
    for (int mf = 0; mf < 2; mf++)
#pragma unroll
        for (int nf = 0; nf < 8; nf++)
#pragma unroll
            for (int q = 0; q < 4; q++) {
                int row = wm + mf * 16 + gid + ((q >> 1) << 3);
                int col = wn + nf * 8 + tg * 2 + (q & 1);
                Gs[row * 132 + col] = c[mf][nf][q];
            }
    __syncthreads();

    float* Hwr = d_H + (size_t)(par ^ 1) * BB * HID;
    const bool last = (s == SEQ - 1);
    for (int i = tid; i < 128 * 32; i += 256) {
        int m = i >> 5, nn = i & 31;
        int mg = m0 + m, ng = n0 + nn;
        float gi = Gs[m * 132 + nn]      + d_bc[ng];
        float gf = Gs[m * 132 + 32 + nn] + d_bc[HID + ng];
        float gg = Gs[m * 132 + 64 + nn] + d_bc[2 * HID + ng];
        float go = Gs[m * 132 + 96 + nn] + d_bc[3 * HID + ng];
        float si = 1.f / (1.f + __expf(-gi));
        float sf = 1.f / (1.f + __expf(-gf));
        float tg2 = tanhf(gg);
        float so = 1.f / (1.f + __expf(-go));
        size_t off = (size_t)mg * HID + ng;
        float cn = sf * d_C[off] + si * tg2;
        float hn = so * tanhf(cn);
        d_C[off] = cn;
        Hwr[off] = tf32r(hn);
        if (last) d_Hfp[off] = hn;
    }
}

// ---------------- cosine + concat ----------------
__global__ void k_cos() {
    int b = blockIdx.x;
    const int tid = threadIdx.x, lane = tid & 31, warp = tid >> 5;
    const float* p = d_Hfp + (size_t)b * HID;
    const float* h = d_Hfp + (size_t)(BATCH + b) * HID;
    float dot = 0, np = 0, nh = 0;
    for (int k = tid; k < HID; k += 128) {
        float a = p[k], cc = h[k];
        dot += a * cc; np += a * a; nh += cc * cc;
    }
#pragma unroll
    for (int o = 16; o; o >>= 1) {
        dot += __shfl_xor_sync(0xffffffffu, dot, o);
        np  += __shfl_xor_sync(0xffffffffu, np,  o);
        nh  += __shfl_xor_sync(0xffffffffu, nh,  o);
    }
    __shared__ float sd[4], sp[4], sh[4];
    if (lane == 0) { sd[warp] = dot; sp[warp] = np; sh[warp] = nh; }
    __syncthreads();
    float* dst = d_X0 + (size_t)b * SPAD;
    if (tid == 0) {
        dot = sd[0] + sd[1] + sd[2] + sd[3];
        np  = sp[0] + sp[1] + sp[2] + sp[3];
        nh  = sh[0] + sh[1] + sh[2] + sh[3];
        dst[0] = 1.f - dot / (sqrtf(np) * sqrtf(nh));
    }
    for (int k = tid; k < HID; k += 128) {
        dst[1 + k] = p[k];
        dst[1 + HID + k] = h[k];
    }
    if (tid < SPAD - SIN) dst[SIN + tid] = 0.f;
}

// ---------------- batchnorm stats ----------------
__global__ void k_stats(int which, const float* __restrict__ gamma,
                        const float* __restrict__ beta) {
    const float* Y = (which == 0) ? d_X0 : (which == 1) ? d_Y1 : d_Y2;
    int jx = threadIdx.x & 31;
    int j = blockIdx.x * 32 + jx;
    int ty = threadIdx.x >> 5;
    float s = 0.f, s2 = 0.f;
    if (j < SPAD) {
        for (int r = ty; r < BATCH; r += 8) {
            float v = Y[(size_t)r * SPAD + j];
            s += v; s2 += v * v;
        }
    }
    __shared__ float rs[8][32], rs2[8][32];
    rs[ty][jx] = s; rs2[ty][jx] = s2;
    __syncthreads();
    if (ty == 0 && j < SPAD) {
        for (int t = 1; t < 8; t++) { s += rs[t][jx]; s2 += rs2[t][jx]; }
        if (j < SIN) {
            float m = s * (1.f / BATCH);
            float v = s2 * (1.f / BATCH) - m * m;
            float sc = gamma[j] * rsqrtf(v + 1e-5f);
            d_scale[j] = sc; d_shift[j] = beta[j] - m * sc;
        } else { d_scale[j] = 0.f; d_shift[j] = 0.f; }
    }
}

__global__ void k_norm(int which) {
    const float* Y = (which == 0) ? d_X0 : d_Y1;
    int r = blockIdx.x;
    const float* y = Y + (size_t)r * SPAD;
    for (int j = threadIdx.x; j < SPAD; j += blockDim.x) {
        float v = fmaf(y[j], d_scale[j], d_shift[j]);
        float hv = tf32r(v);
        d_NAh[(size_t)r * SPAD + j] = hv;
        d_NAl[(size_t)r * SPAD + j] = tf32r(v - hv);
    }
}

// ---------------- MLP GEMM, 3xTF32: Y = relu(NA @ W^T + b) ----------------
__global__ void __launch_bounds__(256) k_gemm(int layer) {
    extern __shared__ float sm[];
    float* Ah = sm;
    float* Al = sm + 2 * TILEF;
    float* Bh = sm + 4 * TILEF;
    float* Bl = sm + 6 * TILEF;

    const float* Wh = layer ? d_W1h : d_W0h;
    const float* Wl = layer ? d_W1l : d_W0l;
    const float* bias = layer ? d_b1p : d_b0p;
    float* Y = layer ? d_Y2 : d_Y1;

    const int m0 = blockIdx.x * 128;
    const int n0 = blockIdx.y * 128;
    const int tid = threadIdx.x;
    const int lane = tid & 31, warp = tid >> 5;
    const int gid = lane >> 2, tg = lane & 3;
    const int wm = (warp >> 1) * 32;
    const int wn = (warp & 1) * 64;

    float c[2][8][4];
#pragma unroll
    for (int a = 0; a < 2; a++)
#pragma unroll
        for (int b2 = 0; b2 < 8; b2++)
#pragma unroll
            for (int q = 0; q < 4; q++) c[a][b2][q] = 0.f;

    auto loadtile = [&](int it, int buf) {
        int k0 = it * 16;
#pragma unroll
        for (int u = 0; u < 2; u++) {
            int f = tid + u * 256;
            int r = f >> 2, c4 = f & 3;
            size_t oa = (size_t)(m0 + r) * SPAD + k0 + c4 * 4;
            size_t ob = (size_t)(n0 + r) * SPAD + k0 + c4 * 4;
            int so = buf * TILEF + r * BKP + c4 * 4;
            cpa16(Ah + so, d_NAh + oa);
            cpa16(Al + so, d_NAl + oa);
            cpa16(Bh + so, Wh + ob);
            cpa16(Bl + so, Wl + ob);
        }
        cpa_commit();
    };

    auto compute = [&](int buf) {
        const float* ah = Ah + buf * TILEF;
        const float* al = Al + buf * TILEF;
        const float* bh = Bh + buf * TILEF;
        const float* bl = Bl + buf * TILEF;
#pragma unroll
        for (int kk = 0; kk < 16; kk += 8) {
            uint32_t afh[2][4], afl[2][4], bfh[8][2], bfl[8][2];
#pragma unroll
            for (int mf = 0; mf < 2; mf++) {
                int r = wm + mf * 16 + gid;
                afh[mf][0] = __float_as_uint(ah[r * BKP + kk + tg]);
                afh[mf][1] = __float_as_uint(ah[(r + 8) * BKP + kk + tg]);
                afh[mf][2] = __float_as_uint(ah[r * BKP + kk + tg + 4]);
                afh[mf][3] = __float_as_uint(ah[(r + 8) * BKP + kk + tg + 4]);
                afl[mf][0] = __float_as_uint(al[r * BKP + kk + tg]);
                afl[mf][1] = __float_as_uint(al[(r + 8) * BKP + kk + tg]);
                afl[mf][2] = __float_as_uint(al[r * BKP + kk + tg + 4]);
                afl[mf][3] = __float_as_uint(al[(r + 8) * BKP + kk + tg + 4]);
            }
#pragma unroll
            for (int nf = 0; nf < 8; nf++) {
                int n = wn + nf * 8 + gid;
                bfh[nf][0] = __float_as_uint(bh[n * BKP + kk + tg]);
                bfh[nf][1] = __float_as_uint(bh[n * BKP + kk + tg + 4]);
                bfl[nf][0] = __float_as_uint(bl[n * BKP + kk + tg]);
                bfl[nf][1] = __float_as_uint(bl[n * BKP + kk + tg + 4]);
            }
#pragma unroll
            for (int mf = 0; mf < 2; mf++)
#pragma unroll
                for (int nf = 0; nf < 8; nf++) {
                    mma_tf32(c[mf][nf], afh[mf], bfl[nf]);
                    mma_tf32(c[mf][nf], afl[mf], bfh[nf]);
                    mma_tf32(c[mf][nf], afh[mf], bfh[nf]);
                }
        }
    };

    loadtile(0, 0);
#pragma unroll 1
    for (int it = 0; it < NIT_MLP; ++it) {
        if (it + 1 < NIT_MLP) { loadtile(it + 1, (it + 1) & 1); cpa_wait1(); }
        else                  { cpa_wait0(); }
        __syncthreads();
        compute(it & 1);
        __syncthreads();
    }

#pragma unroll
    for (int mf = 0; mf < 2; mf++)
#pragma unroll
        for (int nf = 0; nf < 8; nf++)
#pragma unroll
            for (int q = 0; q < 4; q++) {
                int row = m0 + wm + mf * 16 + gid + ((q >> 1) << 3);
                int col = n0 + wn + nf * 8 + tg * 2 + (q & 1);
                if (col < SPAD) {
                    float v = 0.f;
                    if (col < SIN) v = fmaxf(c[mf][nf][q] + bias[col], 0.f);
                    Y[(size_t)row * SPAD + col] = v;
                }
            }
}

// ---------------- final linear (BN fused inline) ----------------
__global__ void k_final(const float* __restrict__ Wo, const float* __restrict__ blo,
                        float* __restrict__ out) {
    int b = blockIdx.x;
    const int tid = threadIdx.x, lane = tid & 31, warp = tid >> 5;
    const float* y = d_Y2 + (size_t)b * SPAD;
    float s0 = 0, s1 = 0, s2 = 0;
    for (int k = tid; k < SIN; k += 256) {
        float v = fmaf(y[k], d_scale[k], d_shift[k]);
        s0 += v * Wo[k];
        s1 += v * Wo[SIN + k];
        s2 += v * Wo[2 * SIN + k];
    }
#pragma unroll
    for (int o = 16; o; o >>= 1) {
        s0 += __shfl_xor_sync(0xffffffffu, s0, o);
        s1 += __shfl_xor_sync(0xffffffffu, s1, o);
        s2 += __shfl_xor_sync(0xffffffffu, s2, o);
    }
    __shared__ float r0[8], r1[8], r2[8];
    if (lane == 0) { r0[warp] = s0; r1[warp] = s1; r2[warp] = s2; }
    __syncthreads();
    if (tid == 0) {
        float a0 = 0, a1 = 0, a2 = 0;
        for (int w = 0; w < 8; w++) { a0 += r0[w]; a1 += r1[w]; a2 += r2[w]; }
        out[b * 3 + 0] = a0 + blo[0];
        out[b * 3 + 1] = a1 + blo[1];
        out[b * 3 + 2] = a2 + blo[2];
    }
}

// ---------------- host ----------------
extern "C" void kernel_launch(void* const* d_in, const int* in_sizes, int n_in,
                              void* d_out, int out_size) {
    const int*   prem  = (const int*)d_in[0];
    const int*   hyp   = (const int*)d_in[1];
    const float* embed = (const float*)d_in[2];
    const float* Wih   = (const float*)d_in[3];
    const float* Whh   = (const float*)d_in[4];
    const float* bih   = (const float*)d_in[5];
    const float* bhh   = (const float*)d_in[6];
    const float* g0    = (const float*)d_in[7];
    const float* be0   = (const float*)d_in[8];
    const float* W0    = (const float*)d_in[9];
    const float* bl0   = (const float*)d_in[10];
    const float* g1    = (const float*)d_in[11];
    const float* be1   = (const float*)d_in[12];
    const float* W1    = (const float*)d_in[13];
    const float* bl1   = (const float*)d_in[14];
    const float* go    = (const float*)d_in[15];
    const float* beo   = (const float*)d_in[16];
    const float* Wo    = (const float*)d_in[17];
    const float* blo   = (const float*)d_in[18];
    float* out = (float*)d_out;

    const size_t STEP_SMEM = 128 * 132 * sizeof(float);        // 67584 (Gs reuse superset)
    const size_t GEMM_SMEM = 8 * TILEF * sizeof(float);        // 81920

    cudaFuncSetAttribute(k_step, cudaFuncAttributeMaxDynamicSharedMemorySize, (int)STEP_SMEM);
    cudaFuncSetAttribute(k_gemm, cudaFuncAttributeMaxDynamicSharedMemorySize, (int)GEMM_SMEM);

    k_prep<<<1024, 256>>>(Wih, Whh, bih, bhh);
    k_padw<<<1024, 256>>>(W0, 0);
    k_padw<<<1024, 256>>>(W1, 1);
    k_padb<<<5, 256>>>(bl0, 0);
    k_padb<<<5, 256>>>(bl1, 1);
    k_zero<<<1024, 256>>>();
    k_gather<<<SEQ * BB, 64>>>(prem, hyp, embed);

    for (int s = 0; s < SEQ; ++s)
        k_step<<<dim3(BB / 128, HID / 32), 256, STEP_SMEM>>>(s, s & 1);

    k_cos<<<BATCH, 128>>>();

    k_stats<<<(SPAD + 31) / 32, 256>>>(0, g0, be0);
    k_norm<<<BATCH, 256>>>(0);
    k_gemm<<<dim3(BATCH / 128, NROWS / 128), 256, GEMM_SMEM>>>(0);

    k_stats<<<(SPAD + 31) / 32, 256>>>(1, g1, be1);
    k_norm<<<BATCH, 256>>>(1);
    k_gemm<<<dim3(BATCH / 128, NROWS / 128), 256, GEMM_SMEM>>>(1);

    k_stats<<<(SPAD + 31) / 32, 256>>>(2, go, beo);
    k_final<<<BATCH, 256>>>(Wo, blo, out);
}

// round 4
// speedup vs baseline: 1.4938x; 1.4938x over previous
#include <cuda_runtime.h>
#include <cuda_fp16.h>
#include <cstdint>

#define SEQ   48
#define BATCH 4096
#define BB    8192
#define DEMB  300
#define DX    304
#define HID   512
#define G4    2048
#define KTOT  816
#define NIT_STEP 51          // KTOT/16
#define SIN   1025
#define SPAD  1040
#define NROWS 1152
#define NIT_MLP 65
#define BKP   20             // fp32 MLP tile pitch
#define TILEF (128 * BKP)
#define HP    24             // half tile pitch (conflict-free frag LDS)
#define TILEH (128 * HP)

// ---------------- scratch ----------------
__device__ __half d_Xall[(size_t)SEQ * BB * DX];
__device__ __half d_H[2ull * BB * HID];
__device__ float  d_C[(size_t)BB * HID];
__device__ float  d_Hfp[(size_t)BB * HID];
__device__ __half d_Wc[(size_t)G4 * KTOT];
__device__ float  d_bc[G4];
__device__ float  d_X0[(size_t)BATCH * SPAD];
__device__ float  d_Y1[(size_t)BATCH * SPAD];
__device__ float  d_Y2[(size_t)BATCH * SPAD];
__device__ float  d_NAh[(size_t)BATCH * SPAD];
__device__ float  d_NAl[(size_t)BATCH * SPAD];
__device__ float  d_W0h[(size_t)NROWS * SPAD];
__device__ float  d_W0l[(size_t)NROWS * SPAD];
__device__ float  d_W1h[(size_t)NROWS * SPAD];
__device__ float  d_W1l[(size_t)NROWS * SPAD];
__device__ float  d_b0p[NROWS];
__device__ float  d_b1p[NROWS];
__device__ float  d_scale[SPAD];
__device__ float  d_shift[SPAD];

// ---------------- helpers ----------------
__device__ __forceinline__ float tf32r(float x) {
    uint32_t u;
    asm("cvt.rna.tf32.f32 %0, %1;" : "=r"(u) : "f"(x));
    return __uint_as_float(u);
}
__device__ __forceinline__ void cpa16(void* s, const void* g) {
    uint32_t sa = (uint32_t)__cvta_generic_to_shared(s);
    asm volatile("cp.async.ca.shared.global [%0], [%1], 16;\n" :: "r"(sa), "l"(g));
}
__device__ __forceinline__ void cpa_commit() { asm volatile("cp.async.commit_group;\n"); }
__device__ __forceinline__ void cpa_wait1()  { asm volatile("cp.async.wait_group 1;\n"); }
__device__ __forceinline__ void cpa_wait0()  { asm volatile("cp.async.wait_group 0;\n"); }

__device__ __forceinline__ void mma_f16(float* c, const uint32_t* a, const uint32_t* b) {
    asm volatile(
        "mma.sync.aligned.m16n8k16.row.col.f32.f16.f16.f32 "
        "{%0,%1,%2,%3}, {%4,%5,%6,%7}, {%8,%9}, {%0,%1,%2,%3};\n"
        : "+f"(c[0]), "+f"(c[1]), "+f"(c[2]), "+f"(c[3])
        : "r"(a[0]), "r"(a[1]), "r"(a[2]), "r"(a[3]), "r"(b[0]), "r"(b[1]));
}
__device__ __forceinline__ void mma_tf32(float* c, const uint32_t* a, const uint32_t* b) {
    asm volatile(
        "mma.sync.aligned.m16n8k8.row.col.f32.tf32.tf32.f32 "
        "{%0,%1,%2,%3}, {%4,%5,%6,%7}, {%8,%9}, {%0,%1,%2,%3};\n"
        : "+f"(c[0]), "+f"(c[1]), "+f"(c[2]), "+f"(c[3])
        : "r"(a[0]), "r"(a[1]), "r"(a[2]), "r"(a[3]), "r"(b[0]), "r"(b[1]));
}

// ---------------- prep ----------------
__global__ void k_prep(const float* __restrict__ Wih, const float* __restrict__ Whh,
                       const float* __restrict__ bih, const float* __restrict__ bhh) {
    for (size_t i = (size_t)blockIdx.x * blockDim.x + threadIdx.x;
         i < (size_t)G4 * KTOT; i += (size_t)gridDim.x * blockDim.x) {
        int g = (int)(i / KTOT), k = (int)(i % KTOT);
        float v;
        if (k < HID)              v = Whh[(size_t)g * HID + k];
        else if (k - HID < DEMB)  v = Wih[(size_t)g * DEMB + (k - HID)];
        else                      v = 0.f;
        d_Wc[i] = __float2half_rn(v);
        if (i < G4) d_bc[i] = bih[i] + bhh[i];
    }
}

__global__ void k_padw(const float* __restrict__ src, int which) {
    float* dh = which ? d_W1h : d_W0h;
    float* dl = which ? d_W1l : d_W0l;
    for (size_t i = (size_t)blockIdx.x * blockDim.x + threadIdx.x;
         i < (size_t)NROWS * SPAD; i += (size_t)gridDim.x * blockDim.x) {
        int r = (int)(i / SPAD), c = (int)(i % SPAD);
        float v = (r < SIN && c < SIN) ? src[(size_t)r * SIN + c] : 0.f;
        float h = tf32r(v);
        dh[i] = h;
        dl[i] = tf32r(v - h);
    }
}

__global__ void k_padb(const float* __restrict__ src, int which) {
    float* dst = which ? d_b1p : d_b0p;
    int i = blockIdx.x * blockDim.x + threadIdx.x;
    if (i < NROWS) dst[i] = (i < SIN) ? src[i] : 0.f;
}

__global__ void k_zero() {
    for (size_t i = (size_t)blockIdx.x * blockDim.x + threadIdx.x;
         i < (size_t)BB * HID; i += (size_t)gridDim.x * blockDim.x) {
        d_C[i] = 0.f;
        d_H[i] = __half(0.f);   // par=0 buffer
    }
}

__global__ void k_gather(const int* __restrict__ prem, const int* __restrict__ hyp,
                         const float* __restrict__ embed) {
    int sb = blockIdx.x;
    int s = sb / BB, b = sb % BB;
    int tok = (b < BATCH) ? prem[s * BATCH + b] : hyp[s * BATCH + (b - BATCH)];
    const float* e = embed + (size_t)tok * DEMB;
    __half* dst = d_Xall + (size_t)sb * DX;
    for (int d = threadIdx.x; d < DX; d += blockDim.x)
        dst[d] = (d < DEMB) ? __float2half_rn(e[d]) : __half(0.f);
}

// ---------------- fused LSTM step (fp16 m16n8k16) ----------------
__global__ void __launch_bounds__(256) k_step(int s, int par) {
    extern __shared__ char smc[];
    __half* As = (__half*)smc;            // [2][TILEH]
    __half* Bs = As + 2 * TILEH;          // [2][TILEH]
    float*  Gs = (float*)smc;             // reused after mainloop, pitch 132

    const int m0 = blockIdx.x * 128;
    const int n0 = blockIdx.y * 32;       // h-column base
    const int tid = threadIdx.x;
    const int lane = tid & 31, warp = tid >> 5;
    const int gid = lane >> 2, tg = lane & 3;
    const int wm = (warp >> 1) * 32;      // 4 warps along M
    const int wn = (warp & 1) * 64;       // 2 warps along gate-cols
    const __half* Hrd = d_H + (size_t)par * BB * HID;

    float c[2][8][4];
#pragma unroll
    for (int a = 0; a < 2; a++)
#pragma unroll
        for (int b = 0; b < 8; b++)
#pragma unroll
            for (int q = 0; q < 4; q++) c[a][b][q] = 0.f;

    const int lr = tid >> 1, lc8 = (tid & 1) * 8;   // cp.async coords

    auto loadtile = [&](int it, int buf) {
        int k0 = it * 16;
        __half* Ab = As + buf * TILEH;
        __half* Bb = Bs + buf * TILEH;
        const __half* ga = (k0 < HID)
            ? (Hrd + (size_t)(m0 + lr) * HID + k0 + lc8)
            : (d_Xall + ((size_t)s * BB + m0 + lr) * DX + (k0 - HID) + lc8);
        cpa16(Ab + lr * HP + lc8, ga);
        const __half* gb = d_Wc + (size_t)((lr >> 5) * HID + n0 + (lr & 31)) * KTOT + k0 + lc8;
        cpa16(Bb + lr * HP + lc8, gb);
        cpa_commit();
    };

    auto compute = [&](int buf) {
        const __half* Ab = As + buf * TILEH;
        const __half* Bb = Bs + buf * TILEH;
        uint32_t af[2][4], bf[8][2];
#pragma unroll
        for (int mf = 0; mf < 2; mf++) {
            int r = wm + mf * 16 + gid;
            af[mf][0] = *(const uint32_t*)&Ab[r * HP + 2 * tg];
            af[mf][1] = *(const uint32_t*)&Ab[(r + 8) * HP + 2 * tg];
            af[mf][2] = *(const uint32_t*)&Ab[r * HP + 2 * tg + 8];
            af[mf][3] = *(const uint32_t*)&Ab[(r + 8) * HP + 2 * tg + 8];
        }
#pragma unroll
        for (int nf = 0; nf < 8; nf++) {
            int n = wn + nf * 8 + gid;
            bf[nf][0] = *(const uint32_t*)&Bb[n * HP + 2 * tg];
            bf[nf][1] = *(const uint32_t*)&Bb[n * HP + 2 * tg + 8];
        }
#pragma unroll
        for (int mf = 0; mf < 2; mf++)
#pragma unroll
            for (int nf = 0; nf < 8; nf++)
                mma_f16(c[mf][nf], af[mf], bf[nf]);
    };

    loadtile(0, 0);
#pragma unroll 1
    for (int it = 0; it < NIT_STEP; ++it) {
        if (it + 1 < NIT_STEP) { loadtile(it + 1, (it + 1) & 1); cpa_wait1(); }
        else                   { cpa_wait0(); }
        __syncthreads();
        compute(it & 1);
        __syncthreads();
    }

    // regroup gates through smem (Gs overlaps operand buffers; last sync protects)
#pragma unroll
    for (int mf = 0; mf < 2; mf++)
#pragma unroll
        for (int nf = 0; nf < 8; nf++)
#pragma unroll
            for (int q = 0; q < 4; q++) {
                int row = wm + mf * 16 + gid + ((q >> 1) << 3);
                int col = wn + nf * 8 + tg * 2 + (q & 1);
                Gs[row * 132 + col] = c[mf][nf][q];
            }
    __syncthreads();

    __half* Hwr = d_H + (size_t)(par ^ 1) * BB * HID;
    const bool last = (s == SEQ - 1);
    for (int i = tid; i < 128 * 32; i += 256) {
        int m = i >> 5, nn = i & 31;
        int mg = m0 + m, ng = n0 + nn;
        float gi = Gs[m * 132 + nn]      + d_bc[ng];
        float gf = Gs[m * 132 + 32 + nn] + d_bc[HID + ng];
        float gg = Gs[m * 132 + 64 + nn] + d_bc[2 * HID + ng];
        float go = Gs[m * 132 + 96 + nn] + d_bc[3 * HID + ng];
        float si = 1.f / (1.f + __expf(-gi));
        float sf = 1.f / (1.f + __expf(-gf));
        float tg2 = tanhf(gg);
        float so = 1.f / (1.f + __expf(-go));
        size_t off = (size_t)mg * HID + ng;
        float cn = sf * d_C[off] + si * tg2;
        float hn = so * tanhf(cn);
        d_C[off] = cn;
        Hwr[off] = __float2half_rn(hn);
        if (last) d_Hfp[off] = hn;
    }
}

// ---------------- cosine + concat ----------------
__global__ void k_cos() {
    int b = blockIdx.x;
    const int tid = threadIdx.x, lane = tid & 31, warp = tid >> 5;
    const float* p = d_Hfp + (size_t)b * HID;
    const float* h = d_Hfp + (size_t)(BATCH + b) * HID;
    float dot = 0, np = 0, nh = 0;
    for (int k = tid; k < HID; k += 128) {
        float a = p[k], cc = h[k];
        dot += a * cc; np += a * a; nh += cc * cc;
    }
#pragma unroll
    for (int o = 16; o; o >>= 1) {
        dot += __shfl_xor_sync(0xffffffffu, dot, o);
        np  += __shfl_xor_sync(0xffffffffu, np,  o);
        nh  += __shfl_xor_sync(0xffffffffu, nh,  o);
    }
    __shared__ float sd[4], sp[4], sh[4];
    if (lane == 0) { sd[warp] = dot; sp[warp] = np; sh[warp] = nh; }
    __syncthreads();
    float* dst = d_X0 + (size_t)b * SPAD;
    if (tid == 0) {
        dot = sd[0] + sd[1] + sd[2] + sd[3];
        np  = sp[0] + sp[1] + sp[2] + sp[3];
        nh  = sh[0] + sh[1] + sh[2] + sh[3];
        dst[0] = 1.f - dot / (sqrtf(np) * sqrtf(nh));
    }
    for (int k = tid; k < HID; k += 128) {
        dst[1 + k] = p[k];
        dst[1 + HID + k] = h[k];
    }
    if (tid < SPAD - SIN) dst[SIN + tid] = 0.f;
}

// ---------------- batchnorm stats ----------------
__global__ void k_stats(int which, const float* __restrict__ gamma,
                        const float* __restrict__ beta) {
    const float* Y = (which == 0) ? d_X0 : (which == 1) ? d_Y1 : d_Y2;
    int jx = threadIdx.x & 31;
    int j = blockIdx.x * 32 + jx;
    int ty = threadIdx.x >> 5;
    float s = 0.f, s2 = 0.f;
    if (j < SPAD) {
        for (int r = ty; r < BATCH; r += 8) {
            float v = Y[(size_t)r * SPAD + j];
            s += v; s2 += v * v;
        }
    }
    __shared__ float rs[8][32], rs2[8][32];
    rs[ty][jx] = s; rs2[ty][jx] = s2;
    __syncthreads();
    if (ty == 0 && j < SPAD) {
        for (int t = 1; t < 8; t++) { s += rs[t][jx]; s2 += rs2[t][jx]; }
        if (j < SIN) {
            float m = s * (1.f / BATCH);
            float v = s2 * (1.f / BATCH) - m * m;
            float sc = gamma[j] * rsqrtf(v + 1e-5f);
            d_scale[j] = sc; d_shift[j] = beta[j] - m * sc;
        } else { d_scale[j] = 0.f; d_shift[j] = 0.f; }
    }
}

__global__ void k_norm(int which) {
    const float* Y = (which == 0) ? d_X0 : d_Y1;
    int r = blockIdx.x;
    const float* y = Y + (size_t)r * SPAD;
    for (int j = threadIdx.x; j < SPAD; j += blockDim.x) {
        float v = fmaf(y[j], d_scale[j], d_shift[j]);
        float hv = tf32r(v);
        d_NAh[(size_t)r * SPAD + j] = hv;
        d_NAl[(size_t)r * SPAD + j] = tf32r(v - hv);
    }
}

// ---------------- MLP GEMM, 3xTF32 ----------------
__global__ void __launch_bounds__(256) k_gemm(int layer) {
    extern __shared__ float sm[];
    float* Ah = sm;
    float* Al = sm + 2 * TILEF;
    float* Bh = sm + 4 * TILEF;
    float* Bl = sm + 6 * TILEF;

    const float* Wh = layer ? d_W1h : d_W0h;
    const float* Wl = layer ? d_W1l : d_W0l;
    const float* bias = layer ? d_b1p : d_b0p;
    float* Y = layer ? d_Y2 : d_Y1;

    const int m0 = blockIdx.x * 128;
    const int n0 = blockIdx.y * 128;
    const int tid = threadIdx.x;
    const int lane = tid & 31, warp = tid >> 5;
    const int gid = lane >> 2, tg = lane & 3;
    const int wm = (warp >> 1) * 32;
    const int wn = (warp & 1) * 64;

    float c[2][8][4];
#pragma unroll
    for (int a = 0; a < 2; a++)
#pragma unroll
        for (int b2 = 0; b2 < 8; b2++)
#pragma unroll
            for (int q = 0; q < 4; q++) c[a][b2][q] = 0.f;

    auto loadtile = [&](int it, int buf) {
        int k0 = it * 16;
#pragma unroll
        for (int u = 0; u < 2; u++) {
            int f = tid + u * 256;
            int r = f >> 2, c4 = f & 3;
            size_t oa = (size_t)(m0 + r) * SPAD + k0 + c4 * 4;
            size_t ob = (size_t)(n0 + r) * SPAD + k0 + c4 * 4;
            int so = buf * TILEF + r * BKP + c4 * 4;
            cpa16(Ah + so, d_NAh + oa);
            cpa16(Al + so, d_NAl + oa);
            cpa16(Bh + so, Wh + ob);
            cpa16(Bl + so, Wl + ob);
        }
        cpa_commit();
    };

    auto compute = [&](int buf) {
        const float* ah = Ah + buf * TILEF;
        const float* al = Al + buf * TILEF;
        const float* bh = Bh + buf * TILEF;
        const float* bl = Bl + buf * TILEF;
#pragma unroll
        for (int kk = 0; kk < 16; kk += 8) {
            uint32_t afh[2][4], afl[2][4], bfh[8][2], bfl[8][2];
#pragma unroll
            for (int mf = 0; mf < 2; mf++) {
                int r = wm + mf * 16 + gid;
                afh[mf][0] = __float_as_uint(ah[r * BKP + kk + tg]);
                afh[mf][1] = __float_as_uint(ah[(r + 8) * BKP + kk + tg]);
                afh[mf][2] = __float_as_uint(ah[r * BKP + kk + tg + 4]);
                afh[mf][3] = __float_as_uint(ah[(r + 8) * BKP + kk + tg + 4]);
                afl[mf][0] = __float_as_uint(al[r * BKP + kk + tg]);
                afl[mf][1] = __float_as_uint(al[(r + 8) * BKP + kk + tg]);
                afl[mf][2] = __float_as_uint(al[r * BKP + kk + tg + 4]);
                afl[mf][3] = __float_as_uint(al[(r + 8) * BKP + kk + tg + 4]);
            }
#pragma unroll
            for (int nf = 0; nf < 8; nf++) {
                int n = wn + nf * 8 + gid;
                bfh[nf][0] = __float_as_uint(bh[n * BKP + kk + tg]);
                bfh[nf][1] = __float_as_uint(bh[n * BKP + kk + tg + 4]);
                bfl[nf][0] = __float_as_uint(bl[n * BKP + kk + tg]);
                bfl[nf][1] = __float_as_uint(bl[n * BKP + kk + tg + 4]);
            }
#pragma unroll
            for (int mf = 0; mf < 2; mf++)
#pragma unroll
                for (int nf = 0; nf < 8; nf++) {
                    mma_tf32(c[mf][nf], afh[mf], bfl[nf]);
                    mma_tf32(c[mf][nf], afl[mf], bfh[nf]);
                    mma_tf32(c[mf][nf], afh[mf], bfh[nf]);
                }
        }
    };

    loadtile(0, 0);
#pragma unroll 1
    for (int it = 0; it < NIT_MLP; ++it) {
        if (it + 1 < NIT_MLP) { loadtile(it + 1, (it + 1) & 1); cpa_wait1(); }
        else                  { cpa_wait0(); }
        __syncthreads();
        compute(it & 1);
        __syncthreads();
    }

#pragma unroll
    for (int mf = 0; mf < 2; mf++)
#pragma unroll
        for (int nf = 0; nf < 8; nf++)
#pragma unroll
            for (int q = 0; q < 4; q++) {
                int row = m0 + wm + mf * 16 + gid + ((q >> 1) << 3);
                int col = n0 + wn + nf * 8 + tg * 2 + (q & 1);
                if (col < SPAD) {
                    float v = 0.f;
                    if (col < SIN) v = fmaxf(c[mf][nf][q] + bias[col], 0.f);
                    Y[(size_t)row * SPAD + col] = v;
                }
            }
}

// ---------------- final linear (BN fused inline) ----------------
__global__ void k_final(const float* __restrict__ Wo, const float* __restrict__ blo,
                        float* __restrict__ out) {
    int b = blockIdx.x;
    const int tid = threadIdx.x, lane = tid & 31, warp = tid >> 5;
    const float* y = d_Y2 + (size_t)b * SPAD;
    float s0 = 0, s1 = 0, s2 = 0;
    for (int k = tid; k < SIN; k += 256) {
        float v = fmaf(y[k], d_scale[k], d_shift[k]);
        s0 += v * Wo[k];
        s1 += v * Wo[SIN + k];
        s2 += v * Wo[2 * SIN + k];
    }
#pragma unroll
    for (int o = 16; o; o >>= 1) {
        s0 += __shfl_xor_sync(0xffffffffu, s0, o);
        s1 += __shfl_xor_sync(0xffffffffu, s1, o);
        s2 += __shfl_xor_sync(0xffffffffu, s2, o);
    }
    __shared__ float r0[8], r1[8], r2[8];
    if (lane == 0) { r0[warp] = s0; r1[warp] = s1; r2[warp] = s2; }
    __syncthreads();
    if (tid == 0) {
        float a0 = 0, a1 = 0, a2 = 0;
        for (int w = 0; w < 8; w++) { a0 += r0[w]; a1 += r1[w]; a2 += r2[w]; }
        out[b * 3 + 0] = a0 + blo[0];
        out[b * 3 + 1] = a1 + blo[1];
        out[b * 3 + 2] = a2 + blo[2];
    }
}

// ---------------- host ----------------
extern "C" void kernel_launch(void* const* d_in, const int* in_sizes, int n_in,
                              void* d_out, int out_size) {
    const int*   prem  = (const int*)d_in[0];
    const int*   hyp   = (const int*)d_in[1];
    const float* embed = (const float*)d_in[2];
    const float* Wih   = (const float*)d_in[3];
    const float* Whh   = (const float*)d_in[4];
    const float* bih   = (const float*)d_in[5];
    const float* bhh   = (const float*)d_in[6];
    const float* g0    = (const float*)d_in[7];
    const float* be0   = (const float*)d_in[8];
    const float* W0    = (const float*)d_in[9];
    const float* bl0   = (const float*)d_in[10];
    const float* g1    = (const float*)d_in[11];
    const float* be1   = (const float*)d_in[12];
    const float* W1    = (const float*)d_in[13];
    const float* bl1   = (const float*)d_in[14];
    const float* go    = (const float*)d_in[15];
    const float* beo   = (const float*)d_in[16];
    const float* Wo    = (const float*)d_in[17];
    const float* blo   = (const float*)d_in[18];
    float* out = (float*)d_out;

    const size_t STEP_SMEM = 128 * 132 * sizeof(float);   // 67584 (Gs superset of operands)
    const size_t GEMM_SMEM = 8 * TILEF * sizeof(float);   // 81920

    cudaFuncSetAttribute(k_step, cudaFuncAttributeMaxDynamicSharedMemorySize, (int)STEP_SMEM);
    cudaFuncSetAttribute(k_gemm, cudaFuncAttributeMaxDynamicSharedMemorySize, (int)GEMM_SMEM);

    k_prep<<<1024, 256>>>(Wih, Whh, bih, bhh);
    k_padw<<<1024, 256>>>(W0, 0);
    k_padw<<<1024, 256>>>(W1, 1);
    k_padb<<<5, 256>>>(bl0, 0);
    k_padb<<<5, 256>>>(bl1, 1);
    k_zero<<<1024, 256>>>();
    k_gather<<<SEQ * BB, 64>>>(prem, hyp, embed);

    for (int s = 0; s < SEQ; ++s)
        k_step<<<dim3(BB / 128, HID / 32), 256, STEP_SMEM>>>(s, s & 1);

    k_cos<<<BATCH, 128>>>();

    k_stats<<<(SPAD + 31) / 32, 256>>>(0, g0, be0);
    k_norm<<<BATCH, 256>>>(0);
    k_gemm<<<dim3(BATCH / 128, NROWS / 128), 256, GEMM_SMEM>>>(0);

    k_stats<<<(SPAD + 31) / 32, 256>>>(1, g1, be1);
    k_norm<<<BATCH, 256>>>(1);
    k_gemm<<<dim3(BATCH / 128, NROWS / 128), 256, GEMM_SMEM>>>(1);

    k_stats<<<(SPAD + 31) / 32, 256>>>(2, go, beo);
    k_final<<<BATCH, 256>>>(Wo, blo, out);
}

// round 12
// speedup vs baseline: 1.6770x; 1.1227x over previous
#include <cuda_runtime.h>
#include <cuda_fp16.h>
#include <cstdint>

#define SEQ   48
#define BATCH 4096
#define BB    8192
#define DEMB  300
#define DX    304
#define HID   512
#define G4    2048
#define KTOT  816
#define BK    48
#define NIT_STEP 17          // KTOT/BK
#define HP3   56             // step tile pitch (halves)
#define TILE3 (128 * HP3)
#define SIN   1025
#define SPAD  1040
#define NROWS 1152
#define NIT_MLP 65
#define BKP   20             // fp32 MLP tile pitch
#define TILEF (128 * BKP)

// ---------------- scratch ----------------
__device__ __half d_Xall[(size_t)SEQ * BB * DX];
__device__ __half d_H[2ull * BB * HID];
__device__ float  d_C[(size_t)BB * HID];
__device__ float  d_Hfp[(size_t)BB * HID];
__device__ __half d_Wc[(size_t)G4 * KTOT];
__device__ float  d_bc[G4];
__device__ float  d_X0[(size_t)BATCH * SPAD];
__device__ float  d_Y1[(size_t)BATCH * SPAD];
__device__ float  d_Y2[(size_t)BATCH * SPAD];
__device__ float  d_NAh[(size_t)BATCH * SPAD];
__device__ float  d_NAl[(size_t)BATCH * SPAD];
__device__ float  d_W0h[(size_t)NROWS * SPAD];
__device__ float  d_W0l[(size_t)NROWS * SPAD];
__device__ float  d_W1h[(size_t)NROWS * SPAD];
__device__ float  d_W1l[(size_t)NROWS * SPAD];
__device__ float  d_b0p[NROWS];
__device__ float  d_b1p[NROWS];
__device__ float  d_scale[SPAD];
__device__ float  d_shift[SPAD];

// ---------------- helpers ----------------
__device__ __forceinline__ float tf32r(float x) {
    uint32_t u;
    asm("cvt.rna.tf32.f32 %0, %1;" : "=r"(u) : "f"(x));
    return __uint_as_float(u);
}
__device__ __forceinline__ void cpa16(void* s, const void* g) {
    uint32_t sa = (uint32_t)__cvta_generic_to_shared(s);
    asm volatile("cp.async.ca.shared.global [%0], [%1], 16;\n" :: "r"(sa), "l"(g));
}
__device__ __forceinline__ void cpa_commit() { asm volatile("cp.async.commit_group;\n"); }
__device__ __forceinline__ void cpa_wait1()  { asm volatile("cp.async.wait_group 1;\n"); }
__device__ __forceinline__ void cpa_wait0()  { asm volatile("cp.async.wait_group 0;\n"); }

__device__ __forceinline__ void mma_f16(float* c, const uint32_t* a, const uint32_t* b) {
    asm volatile(
        "mma.sync.aligned.m16n8k16.row.col.f32.f16.f16.f32 "
        "{%0,%1,%2,%3}, {%4,%5,%6,%7}, {%8,%9}, {%0,%1,%2,%3};\n"
        : "+f"(c[0]), "+f"(c[1]), "+f"(c[2]), "+f"(c[3])
        : "r"(a[0]), "r"(a[1]), "r"(a[2]), "r"(a[3]), "r"(b[0]), "r"(b[1]));
}
__device__ __forceinline__ void mma_tf32(float* c, const uint32_t* a, const uint32_t* b) {
    asm volatile(
        "mma.sync.aligned.m16n8k8.row.col.f32.tf32.tf32.f32 "
        "{%0,%1,%2,%3}, {%4,%5,%6,%7}, {%8,%9}, {%0,%1,%2,%3};\n"
        : "+f"(c[0]), "+f"(c[1]), "+f"(c[2]), "+f"(c[3])
        : "r"(a[0]), "r"(a[1]), "r"(a[2]), "r"(a[3]), "r"(b[0]), "r"(b[1]));
}

// ---------------- prep ----------------
__global__ void k_prep(const float* __restrict__ Wih, const float* __restrict__ Whh,
                       const float* __restrict__ bih, const float* __restrict__ bhh) {
    for (size_t i = (size_t)blockIdx.x * blockDim.x + threadIdx.x;
         i < (size_t)G4 * KTOT; i += (size_t)gridDim.x * blockDim.x) {
        int g = (int)(i / KTOT), k = (int)(i % KTOT);
        float v;
        if (k < HID)              v = Whh[(size_t)g * HID + k];
        else if (k - HID < DEMB)  v = Wih[(size_t)g * DEMB + (k - HID)];
        else                      v = 0.f;
        d_Wc[i] = __float2half_rn(v);
        if (i < G4) d_bc[i] = bih[i] + bhh[i];
    }
}

__global__ void k_padw(const float* __restrict__ src, int which) {
    float* dh = which ? d_W1h : d_W0h;
    float* dl = which ? d_W1l : d_W0l;
    for (size_t i = (size_t)blockIdx.x * blockDim.x + threadIdx.x;
         i < (size_t)NROWS * SPAD; i += (size_t)gridDim.x * blockDim.x) {
        int r = (int)(i / SPAD), c = (int)(i % SPAD);
        float v = (r < SIN && c < SIN) ? src[(size_t)r * SIN + c] : 0.f;
        float h = tf32r(v);
        dh[i] = h;
        dl[i] = tf32r(v - h);
    }
}

__global__ void k_padb(const float* __restrict__ src, int which) {
    float* dst = which ? d_b1p : d_b0p;
    int i = blockIdx.x * blockDim.x + threadIdx.x;
    if (i < NROWS) dst[i] = (i < SIN) ? src[i] : 0.f;
}

__global__ void k_zero() {
    for (size_t i = (size_t)blockIdx.x * blockDim.x + threadIdx.x;
         i < (size_t)BB * HID; i += (size_t)gridDim.x * blockDim.x) {
        d_C[i] = 0.f;
        d_H[i] = __half(0.f);   // par=0 buffer
    }
}

__global__ void k_gather(const int* __restrict__ prem, const int* __restrict__ hyp,
                         const float* __restrict__ embed) {
    int sb = blockIdx.x;
    int s = sb / BB, b = sb % BB;
    int tok = (b < BATCH) ? prem[s * BATCH + b] : hyp[s * BATCH + (b - BATCH)];
    const float* e = embed + (size_t)tok * DEMB;
    __half* dst = d_Xall + (size_t)sb * DX;
    for (int d = threadIdx.x; d < DX; d += blockDim.x)
        dst[d] = (d < DEMB) ? __float2half_rn(e[d]) : __half(0.f);
}

// ---------------- fused LSTM step (fp16 m16n8k16, BK=48, 3-stage, 1 sync/iter) --
__global__ void __launch_bounds__(256) k_step(int s, int par) {
    extern __shared__ char smc[];
    __half* As = (__half*)smc;            // [3][TILE3]
    __half* Bs = As + 3 * TILE3;          // [3][TILE3]
    float*  Gs = (float*)smc;             // reused after mainloop, pitch 132

    const int m0 = blockIdx.x * 128;
    const int n0 = blockIdx.y * 32;       // h-column base
    const int tid = threadIdx.x;
    const int lane = tid & 31, warp = tid >> 5;
    const int gid = lane >> 2, tg = lane & 3;
    const int wm = (warp >> 1) * 32;      // 4 warps along M
    const int wn = (warp & 1) * 64;       // 2 warps along gate-cols
    const __half* Hrd = d_H + (size_t)par * BB * HID;

    float c[2][8][4];
#pragma unroll
    for (int a = 0; a < 2; a++)
#pragma unroll
        for (int b = 0; b < 8; b++)
#pragma unroll
            for (int q = 0; q < 4; q++) c[a][b][q] = 0.f;

    auto loadtile = [&](int it, int buf) {
        int k0 = it * BK;
        __half* Ab = As + buf * TILE3;
        __half* Bb = Bs + buf * TILE3;
#pragma unroll
        for (int u = 0; u < 3; u++) {
            int f = tid + u * 256;            // 0..767
            int row = f / 6, ch = f % 6;      // 128 rows x 6 chunks of 16B
            int k = k0 + ch * 8;
            const __half* ga = (k < HID)
                ? (Hrd + (size_t)(m0 + row) * HID + k)
                : (d_Xall + ((size_t)s * BB + m0 + row) * DX + (k - HID));
            cpa16(Ab + row * HP3 + ch * 8, ga);
            const __half* gb = d_Wc + (size_t)((row >> 5) * HID + n0 + (row & 31)) * KTOT + k;
            cpa16(Bb + row * HP3 + ch * 8, gb);
        }
        cpa_commit();
    };

    auto compute = [&](int buf) {
        const __half* Ab = As + buf * TILE3;
        const __half* Bb = Bs + buf * TILE3;
#pragma unroll
        for (int kk = 0; kk < BK; kk += 16) {
            uint32_t af[2][4], bf[8][2];
#pragma unroll
            for (int mf = 0; mf < 2; mf++) {
                int r = wm + mf * 16 + gid;
                af[mf][0] = *(const uint32_t*)&Ab[r * HP3 + kk + 2 * tg];
                af[mf][1] = *(const uint32_t*)&Ab[(r + 8) * HP3 + kk + 2 * tg];
                af[mf][2] = *(const uint32_t*)&Ab[r * HP3 + kk + 2 * tg + 8];
                af[mf][3] = *(const uint32_t*)&Ab[(r + 8) * HP3 + kk + 2 * tg + 8];
            }
#pragma unroll
            for (int nf = 0; nf < 8; nf++) {
                int n = wn + nf * 8 + gid;
                bf[nf][0] = *(const uint32_t*)&Bb[n * HP3 + kk + 2 * tg];
                bf[nf][1] = *(const uint32_t*)&Bb[n * HP3 + kk + 2 * tg + 8];
            }
#pragma unroll
            for (int mf = 0; mf < 2; mf++)
#pragma unroll
                for (int nf = 0; nf < 8; nf++)
                    mma_f16(c[mf][nf], af[mf], bf[nf]);
        }
    };

    loadtile(0, 0);
    loadtile(1, 1);
#pragma unroll 1
    for (int it = 0; it < NIT_STEP; ++it) {
        if (it == NIT_STEP - 1) cpa_wait0(); else cpa_wait1();
        __syncthreads();   // tile `it` visible to all; compute(it-1) done before overwrite
        if (it + 2 < NIT_STEP) loadtile(it + 2, (it + 2) % 3);
        compute(it % 3);
    }
    __syncthreads();       // all warps done reading operand smem before Gs overwrite

    // regroup gates through smem
#pragma unroll
    for (int mf = 0; mf < 2; mf++)
#pragma unroll
        for (int nf = 0; nf < 8; nf++)
#pragma unroll
            for (int q = 0; q < 4; q++) {
                int row = wm + mf * 16 + gid + ((q >> 1) << 3);
                int col = wn + nf * 8 + tg * 2 + (q & 1);
                Gs[row * 132 + col] = c[mf][nf][q];
            }
    __syncthreads();

    __half* Hwr = d_H + (size_t)(par ^ 1) * BB * HID;
    const bool last = (s == SEQ - 1);
    for (int i = tid; i < 128 * 32; i += 256) {
        int m = i >> 5, nn = i & 31;
        int mg = m0 + m, ng = n0 + nn;
        float gi = Gs[m * 132 + nn]      + d_bc[ng];
        float gf = Gs[m * 132 + 32 + nn] + d_bc[HID + ng];
        float gg = Gs[m * 132 + 64 + nn] + d_bc[2 * HID + ng];
        float go = Gs[m * 132 + 96 + nn] + d_bc[3 * HID + ng];
        float si = 1.f / (1.f + __expf(-gi));
        float sf = 1.f / (1.f + __expf(-gf));
        float tg2 = tanhf(gg);
        float so = 1.f / (1.f + __expf(-go));
        size_t off = (size_t)mg * HID + ng;
        float cn = sf * d_C[off] + si * tg2;
        float hn = so * tanhf(cn);
        d_C[off] = cn;
        Hwr[off] = __float2half_rn(hn);
        if (last) d_Hfp[off] = hn;
    }
}

// ---------------- cosine + concat ----------------
__global__ void k_cos() {
    int b = blockIdx.x;
    const int tid = threadIdx.x, lane = tid & 31, warp = tid >> 5;
    const float* p = d_Hfp + (size_t)b * HID;
    const float* h = d_Hfp + (size_t)(BATCH + b) * HID;
    float dot = 0, np = 0, nh = 0;
    for (int k = tid; k < HID; k += 128) {
        float a = p[k], cc = h[k];
        dot += a * cc; np += a * a; nh += cc * cc;
    }
#pragma unroll
    for (int o = 16; o; o >>= 1) {
        dot += __shfl_xor_sync(0xffffffffu, dot, o);
        np  += __shfl_xor_sync(0xffffffffu, np,  o);
        nh  += __shfl_xor_sync(0xffffffffu, nh,  o);
    }
    __shared__ float sd[4], sp[4], sh[4];
    if (lane == 0) { sd[warp] = dot; sp[warp] = np; sh[warp] = nh; }
    __syncthreads();
    float* dst = d_X0 + (size_t)b * SPAD;
    if (tid == 0) {
        dot = sd[0] + sd[1] + sd[2] + sd[3];
        np  = sp[0] + sp[1] + sp[2] + sp[3];
        nh  = sh[0] + sh[1] + sh[2] + sh[3];
        dst[0] = 1.f - dot / (sqrtf(np) * sqrtf(nh));
    }
    for (int k = tid; k < HID; k += 128) {
        dst[1 + k] = p[k];
        dst[1 + HID + k] = h[k];
    }
    if (tid < SPAD - SIN) dst[SIN + tid] = 0.f;
}

// ---------------- batchnorm stats ----------------
__global__ void k_stats(int which, const float* __restrict__ gamma,
                        const float* __restrict__ beta) {
    const float* Y = (which == 0) ? d_X0 : (which == 1) ? d_Y1 : d_Y2;
    int jx = threadIdx.x & 31;
    int j = blockIdx.x * 32 + jx;
    int ty = threadIdx.x >> 5;
    float s = 0.f, s2 = 0.f;
    if (j < SPAD) {
        for (int r = ty; r < BATCH; r += 8) {
            float v = Y[(size_t)r * SPAD + j];
            s += v; s2 += v * v;
        }
    }
    __shared__ float rs[8][32], rs2[8][32];
    rs[ty][jx] = s; rs2[ty][jx] = s2;
    __syncthreads();
    if (ty == 0 && j < SPAD) {
        for (int t = 1; t < 8; t++) { s += rs[t][jx]; s2 += rs2[t][jx]; }
        if (j < SIN) {
            float m = s * (1.f / BATCH);
            float v = s2 * (1.f / BATCH) - m * m;
            float sc = gamma[j] * rsqrtf(v + 1e-5f);
            d_scale[j] = sc; d_shift[j] = beta[j] - m * sc;
        } else { d_scale[j] = 0.f; d_shift[j] = 0.f; }
    }
}

__global__ void k_norm(int which) {
    const float* Y = (which == 0) ? d_X0 : d_Y1;
    int r = blockIdx.x;
    const float* y = Y + (size_t)r * SPAD;
    for (int j = threadIdx.x; j < SPAD; j += blockDim.x) {
        float v = fmaf(y[j], d_scale[j], d_shift[j]);
        float hv = tf32r(v);
        d_NAh[(size_t)r * SPAD + j] = hv;
        d_NAl[(size_t)r * SPAD + j] = tf32r(v - hv);
    }
}

// ---------------- MLP GEMM, 3xTF32 ----------------
__global__ void __launch_bounds__(256) k_gemm(int layer) {
    extern __shared__ float sm[];
    float* Ah = sm;
    float* Al = sm + 2 * TILEF;
    float* Bh = sm + 4 * TILEF;
    float* Bl = sm + 6 * TILEF;

    const float* Wh = layer ? d_W1h : d_W0h;
    const float* Wl = layer ? d_W1l : d_W0l;
    const float* bias = layer ? d_b1p : d_b0p;
    float* Y = layer ? d_Y2 : d_Y1;

    const int m0 = blockIdx.x * 128;
    const int n0 = blockIdx.y * 128;
    const int tid = threadIdx.x;
    const int lane = tid & 31, warp = tid >> 5;
    const int gid = lane >> 2, tg = lane & 3;
    const int wm = (warp >> 1) * 32;
    const int wn = (warp & 1) * 64;

    float c[2][8][4];
#pragma unroll
    for (int a = 0; a < 2; a++)
#pragma unroll
        for (int b2 = 0; b2 < 8; b2++)
#pragma unroll
            for (int q = 0; q < 4; q++) c[a][b2][q] = 0.f;

    auto loadtile = [&](int it, int buf) {
        int k0 = it * 16;
#pragma unroll
        for (int u = 0; u < 2; u++) {
            int f = tid + u * 256;
            int r = f >> 2, c4 = f & 3;
            size_t oa = (size_t)(m0 + r) * SPAD + k0 + c4 * 4;
            size_t ob = (size_t)(n0 + r) * SPAD + k0 + c4 * 4;
            int so = buf * TILEF + r * BKP + c4 * 4;
            cpa16(Ah + so, d_NAh + oa);
            cpa16(Al + so, d_NAl + oa);
            cpa16(Bh + so, Wh + ob);
            cpa16(Bl + so, Wl + ob);
        }
        cpa_commit();
    };

    auto compute = [&](int buf) {
        const float* ah = Ah + buf * TILEF;
        const float* al = Al + buf * TILEF;
        const float* bh = Bh + buf * TILEF;
        const float* bl = Bl + buf * TILEF;
#pragma unroll
        for (int kk = 0; kk < 16; kk += 8) {
            uint32_t afh[2][4], afl[2][4], bfh[8][2], bfl[8][2];
#pragma unroll
            for (int mf = 0; mf < 2; mf++) {
                int r = wm + mf * 16 + gid;
                afh[mf][0] = __float_as_uint(ah[r * BKP + kk + tg]);
                afh[mf][1] = __float_as_uint(ah[(r + 8) * BKP + kk + tg]);
                afh[mf][2] = __float_as_uint(ah[r * BKP + kk + tg + 4]);
                afh[mf][3] = __float_as_uint(ah[(r + 8) * BKP + kk + tg + 4]);
                afl[mf][0] = __float_as_uint(al[r * BKP + kk + tg]);
                afl[mf][1] = __float_as_uint(al[(r + 8) * BKP + kk + tg]);
                afl[mf][2] = __float_as_uint(al[r * BKP + kk + tg + 4]);
                afl[mf][3] = __float_as_uint(al[(r + 8) * BKP + kk + tg + 4]);
            }
#pragma unroll
            for (int nf = 0; nf < 8; nf++) {
                int n = wn + nf * 8 + gid;
                bfh[nf][0] = __float_as_uint(bh[n * BKP + kk + tg]);
                bfh[nf][1] = __float_as_uint(bh[n * BKP + kk + tg + 4]);
                bfl[nf][0] = __float_as_uint(bl[n * BKP + kk + tg]);
                bfl[nf][1] = __float_as_uint(bl[n * BKP + kk + tg + 4]);
            }
#pragma unroll
            for (int mf = 0; mf < 2; mf++)
#pragma unroll
                for (int nf = 0; nf < 8; nf++) {
                    mma_tf32(c[mf][nf], afh[mf], bfl[nf]);
                    mma_tf32(c[mf][nf], afl[mf], bfh[nf]);
                    mma_tf32(c[mf][nf], afh[mf], bfh[nf]);
                }
        }
    };

    loadtile(0, 0);
#pragma unroll 1
    for (int it = 0; it < NIT_MLP; ++it) {
        if (it + 1 < NIT_MLP) { loadtile(it + 1, (it + 1) & 1); cpa_wait1(); }
        else                  { cpa_wait0(); }
        __syncthreads();
        compute(it & 1);
        __syncthreads();
    }

#pragma unroll
    for (int mf = 0; mf < 2; mf++)
#pragma unroll
        for (int nf = 0; nf < 8; nf++)
#pragma unroll
            for (int q = 0; q < 4; q++) {
                int row = m0 + wm + mf * 16 + gid + ((q >> 1) << 3);
                int col = n0 + wn + nf * 8 + tg * 2 + (q & 1);
                if (col < SPAD) {
                    float v = 0.f;
                    if (col < SIN) v = fmaxf(c[mf][nf][q] + bias[col], 0.f);
                    Y[(size_t)row * SPAD + col] = v;
                }
            }
}

// ---------------- final linear (BN fused inline) ----------------
__global__ void k_final(const float* __restrict__ Wo, const float* __restrict__ blo,
                        float* __restrict__ out) {
    int b = blockIdx.x;
    const int tid = threadIdx.x, lane = tid & 31, warp = tid >> 5;
    const float* y = d_Y2 + (size_t)b * SPAD;
    float s0 = 0, s1 = 0, s2 = 0;
    for (int k = tid; k < SIN; k += 256) {
        float v = fmaf(y[k], d_scale[k], d_shift[k]);
        s0 += v * Wo[k];
        s1 += v * Wo[SIN + k];
        s2 += v * Wo[2 * SIN + k];
    }
#pragma unroll
    for (int o = 16; o; o >>= 1) {
        s0 += __shfl_xor_sync(0xffffffffu, s0, o);
        s1 += __shfl_xor_sync(0xffffffffu, s1, o);
        s2 += __shfl_xor_sync(0xffffffffu, s2, o);
    }
    __shared__ float r0[8], r1[8], r2[8];
    if (lane == 0) { r0[warp] = s0; r1[warp] = s1; r2[warp] = s2; }
    __syncthreads();
    if (tid == 0) {
        float a0 = 0, a1 = 0, a2 = 0;
        for (int w = 0; w < 8; w++) { a0 += r0[w]; a1 += r1[w]; a2 += r2[w]; }
        out[b * 3 + 0] = a0 + blo[0];
        out[b * 3 + 1] = a1 + blo[1];
        out[b * 3 + 2] = a2 + blo[2];
    }
}

// ---------------- host ----------------
extern "C" void kernel_launch(void* const* d_in, const int* in_sizes, int n_in,
                              void* d_out, int out_size) {
    const int*   prem  = (const int*)d_in[0];
    const int*   hyp   = (const int*)d_in[1];
    const float* embed = (const float*)d_in[2];
    const float* Wih   = (const float*)d_in[3];
    const float* Whh   = (const float*)d_in[4];
    const float* bih   = (const float*)d_in[5];
    const float* bhh   = (const float*)d_in[6];
    const float* g0    = (const float*)d_in[7];
    const float* be0   = (const float*)d_in[8];
    const float* W0    = (const float*)d_in[9];
    const float* bl0   = (const float*)d_in[10];
    const float* g1    = (const float*)d_in[11];
    const float* be1   = (const float*)d_in[12];
    const float* W1    = (const float*)d_in[13];
    const float* bl1   = (const float*)d_in[14];
    const float* go    = (const float*)d_in[15];
    const float* beo   = (const float*)d_in[16];
    const float* Wo    = (const float*)d_in[17];
    const float* blo   = (const float*)d_in[18];
    float* out = (float*)d_out;

    const size_t OPER_SMEM = 6ull * TILE3 * sizeof(__half);          // 86016
    const size_t GS_SMEM   = 128ull * 132 * sizeof(float);           // 67584
    const size_t STEP_SMEM = OPER_SMEM > GS_SMEM ? OPER_SMEM : GS_SMEM;
    const size_t GEMM_SMEM = 8ull * TILEF * sizeof(float);           // 81920

    cudaFuncSetAttribute(k_step, cudaFuncAttributeMaxDynamicSharedMemorySize, (int)STEP_SMEM);
    cudaFuncSetAttribute(k_gemm, cudaFuncAttributeMaxDynamicSharedMemorySize, (int)GEMM_SMEM);

    k_prep<<<1024, 256>>>(Wih, Whh, bih, bhh);
    k_padw<<<1024, 256>>>(W0, 0);
    k_padw<<<1024, 256>>>(W1, 1);
    k_padb<<<5, 256>>>(bl0, 0);
    k_padb<<<5, 256>>>(bl1, 1);
    k_zero<<<1024, 256>>>();
    k_gather<<<SEQ * BB, 64>>>(prem, hyp, embed);

    for (int s = 0; s < SEQ; ++s)
        k_step<<<dim3(BB / 128, HID / 32), 256, STEP_SMEM>>>(s, s & 1);

    k_cos<<<BATCH, 128>>>();

    k_stats<<<(SPAD + 31) / 32, 256>>>(0, g0, be0);
    k_norm<<<BATCH, 256>>>(0);
    k_gemm<<<dim3(BATCH / 128, NROWS / 128), 256, GEMM_SMEM>>>(0);

    k_stats<<<(SPAD + 31) / 32, 256>>>(1, g1, be1);
    k_norm<<<BATCH, 256>>>(1);
    k_gemm<<<dim3(BATCH / 128, NROWS / 128), 256, GEMM_SMEM>>>(1);

    k_stats<<<(SPAD + 31) / 32, 256>>>(2, go, beo);
    k_final<<<BATCH, 256>>>(Wo, blo, out);
}